// round 12
// baseline (speedup 1.0000x reference)
#include <cuda_runtime.h>
#include <math.h>
#include <stdint.h>

#define Bn 64
#define Dn 256
#define Hn 512
#define Rn 32
#define CLIPV 50.0f

// Output layout (concatenation of the returned tuple, fp32):
//   v_new      [64,512]      @ 0
//   new_h      [64,512]      @ 32768
//   dU_new     [64,512,512]  @ 65536
//   new_trace_e[64,512]      @ 16842752
//   new_trace_E[64,512,512]  @ 16875520
#define OFF_V    ((size_t)0)
#define OFF_NH   ((size_t)32768)
#define OFF_DU   ((size_t)65536)
#define OFF_TEO  ((size_t)16842752)
#define OFF_TEE  ((size_t)16875520)

// Device-global scratch (allocation-free; every element fully rewritten
// each launch -> deterministic, graph-replay safe)
__device__ float g_up[Hn * Hn];
__device__ float g_lo[Hn * Hn];
__device__ float g_suMod[Bn];
__device__ float g_sE;
__device__ float g_omU;
__device__ float g_wh[Bn * Hn];        // bias + Wx + Wh per (b,i)
__device__ float g_dvp[Bn * Hn * 4];   // plastic partials, 4 quarters/row

__device__ __forceinline__ float sigmoidf_(float x) {
    return 1.0f / (1.0f + expf(-x));
}

// ---------------------------------------------------------------------------
// K1: one launch, 4480 blocks x 256 threads. Mixed roles by blockIdx.x:
//  [0,64)     Wh blocks: warp-per-i (8 warps/blk), all 64 batches; computes
//             g_wh[b*512+i] = bias_i + x2h_w[i]·x[b] + h2h_w[i]·h[b].
//             ALU/butterfly heavy -> hides under the plastic stream.
//  [64,128)   mod blocks: g_suMod[b] (+ scalars at b==0).
//  [128,384)  uplo blocks: clip bounds, 2 i-rows per block.
//  [384,4480) plastic blocks: p2-SHAPED stream over dU. Warp covers a
//             quarter-row per q-step; computes sum(relu(alpha)*dU*h) with one
//             warp reduce; lane0 writes g_dvp[row*4+quarter]. Deterministic
//             (no atomics), embarrassingly parallel, no inter-row waits.
// Special blocks lead the grid so they start in wave 1.
// ---------------------------------------------------------------------------
#define PL_BLOCKS 4096
#define PL_QTR    ((size_t)1048576)   // (64*512*128)/4 float4 tasks per q

__global__ __launch_bounds__(256) void k1_kernel(
    const float* __restrict__ x, const float* __restrict__ h,
    const float* __restrict__ dU, const float* __restrict__ x2h_w,
    const float* __restrict__ x2h_b, const float* __restrict__ h2h_w,
    const float* __restrict__ h2h_b, const float* __restrict__ alpha,
    const float* __restrict__ tau_U, const float* __restrict__ tau_E) {
    const int bx   = blockIdx.x;
    const int tid  = threadIdx.x;
    const int warp = tid >> 5;
    const int lane = tid & 31;

    if (bx < 64) {
        // ---- Wh blocks: warp w handles i = bx*8 + w over all 64 batches ----
        const int i  = bx * 8 + warp;
        const int jb = lane * 4;
        const float bias = x2h_b[i] + h2h_b[i];
        const float4* wrow4  = (const float4*)(h2h_w + (size_t)i * Hn);
        const float4* xwrow4 = (const float4*)(x2h_w + (size_t)i * Dn);

        for (int b = 0; b < Bn; b++) {
            const float4* hb4 = (const float4*)(h + (size_t)b * Hn);
            const float4* xb4 = (const float4*)(x + (size_t)b * Dn);
            float p0 = 0.f, p1 = 0.f, p2 = 0.f, p3 = 0.f;
#pragma unroll
            for (int c = 0; c < 4; c++) {
                const float4 W4 = __ldg(wrow4 + c * 32 + lane);
                const float4 H4 = __ldg(hb4 + c * 32 + lane);
                p0 = fmaf(W4.x, H4.x, p0);
                p1 = fmaf(W4.y, H4.y, p1);
                p2 = fmaf(W4.z, H4.z, p2);
                p3 = fmaf(W4.w, H4.w, p3);
            }
#pragma unroll
            for (int c = 0; c < 2; c++) {
                const float4 XW = __ldg(xwrow4 + c * 32 + lane);
                const float4 X4 = __ldg(xb4 + c * 32 + lane);
                p0 = fmaf(XW.x, X4.x, p0);
                p1 = fmaf(XW.y, X4.y, p1);
                p2 = fmaf(XW.z, X4.z, p2);
                p3 = fmaf(XW.w, X4.w, p3);
            }
            float p = (p0 + p1) + (p2 + p3);
#pragma unroll
            for (int off = 16; off; off >>= 1)
                p += __shfl_xor_sync(0xffffffffu, p, off);
            if (lane == 0) g_wh[(size_t)b * Hn + i] = p + bias;
        }
        return;
    }

    if (bx < 128) {
        // ---- mod blocks: b = bx - 64; 8 warps x 4 gate rows ----
        const int b = bx - 64;
        __shared__ float sm[8];
        const float4* xb = (const float4*)(x + (size_t)b * Dn);
        const float4* hb = (const float4*)(h + (size_t)b * Hn);

        float acc = 0.f;
#pragma unroll
        for (int t = 0; t < 4; t++) {
            const int r = warp + 8 * t;          // 8 warps x 4 rows = 32
            const int o = Hn + r;
            const float4* xw = (const float4*)(x2h_w + (size_t)o * Dn);
            const float4* hw = (const float4*)(h2h_w + (size_t)o * Hn);
            float s = 0.f;
#pragma unroll
            for (int c = 0; c < 2; c++) {
                const float4 W4 = xw[c * 32 + lane];
                const float4 V4 = xb[c * 32 + lane];
                s = fmaf(W4.x, V4.x, s); s = fmaf(W4.y, V4.y, s);
                s = fmaf(W4.z, V4.z, s); s = fmaf(W4.w, V4.w, s);
            }
#pragma unroll
            for (int c = 0; c < 4; c++) {
                const float4 W4 = hw[c * 32 + lane];
                const float4 V4 = hb[c * 32 + lane];
                s = fmaf(W4.x, V4.x, s); s = fmaf(W4.y, V4.y, s);
                s = fmaf(W4.z, V4.z, s); s = fmaf(W4.w, V4.w, s);
            }
#pragma unroll
            for (int off = 16; off; off >>= 1)
                s += __shfl_xor_sync(0xffffffffu, s, off);
            if (lane == 0) acc += fmaxf(s + x2h_b[o] + h2h_b[o], 0.f);
        }
        if (lane == 0) sm[warp] = acc;
        __syncthreads();
        if (tid == 0) {
            float m = 0.f;
#pragma unroll
            for (int w = 0; w < 8; w++) m += sm[w];
            const float sU = sigmoidf_(tau_U[0]);
            g_suMod[b] = sU * m;
            if (b == 0) {
                g_sE  = sigmoidf_(tau_E[0]);
                g_omU = 1.0f - sU;
            }
        }
        return;
    }

    if (bx < 384) {
        // ---- uplo blocks: 2 i-rows per block ----
        const int i  = (bx - 128) * 2 + (tid >> 7);
        const int j0 = (tid & 127) * 4;
        const float4 W = __ldg((const float4*)(h2h_w + (size_t)i * Hn + j0));
        const float4 A = __ldg((const float4*)(alpha + (size_t)i * Hn + j0));
        float4 up, lo;
        {
            const float d = fmaxf(A.x, 0.f) + 1e-8f;
            up.x = fmaxf(CLIPV - W.x, 0.f) / d;
            lo.x = -fmaxf(CLIPV + W.x, 0.f) / d;
        }
        {
            const float d = fmaxf(A.y, 0.f) + 1e-8f;
            up.y = fmaxf(CLIPV - W.y, 0.f) / d;
            lo.y = -fmaxf(CLIPV + W.y, 0.f) / d;
        }
        {
            const float d = fmaxf(A.z, 0.f) + 1e-8f;
            up.z = fmaxf(CLIPV - W.z, 0.f) / d;
            lo.z = -fmaxf(CLIPV + W.z, 0.f) / d;
        }
        {
            const float d = fmaxf(A.w, 0.f) + 1e-8f;
            up.w = fmaxf(CLIPV - W.w, 0.f) / d;
            lo.w = -fmaxf(CLIPV + W.w, 0.f) / d;
        }
        *(float4*)(g_up + (size_t)i * Hn + j0) = up;
        *(float4*)(g_lo + (size_t)i * Hn + j0) = lo;
        return;
    }

    // ---- plastic blocks: p2-shaped stream over dU ----
    const size_t gid = (size_t)(bx - 384) * 256 + tid;
    const float4* dU4 = (const float4*)dU;
    const float4* a4p = (const float4*)alpha;
    const float4* h4p = (const float4*)h;

#pragma unroll
    for (int q = 0; q < 4; q++) {
        const size_t t = gid + (size_t)q * PL_QTR;
        const int j4  = (int)(t & 127);
        const size_t row = t >> 7;           // b*512 + i
        const int quarter = (int)((t >> 5) & 3);
        const int i = (int)(row & 511);
        const int b = (int)(row >> 9);

        const float4 du = dU4[t];            // default cache: keep in L2 for k3
        const float4 a4 = __ldg(&a4p[((size_t)i << 7) + j4]);
        const float4 h4 = __ldg(&h4p[((size_t)b << 7) + j4]);

        float s;
        s = fmaxf(a4.x, 0.f) * du.x * h4.x;
        s = fmaf(fmaxf(a4.y, 0.f) * du.y, h4.y, s);
        s = fmaf(fmaxf(a4.z, 0.f) * du.z, h4.z, s);
        s = fmaf(fmaxf(a4.w, 0.f) * du.w, h4.w, s);
#pragma unroll
        for (int off = 16; off; off >>= 1)
            s += __shfl_xor_sync(0xffffffffu, s, off);
        if (lane == 0) g_dvp[row * 4 + quarter] = s;  // whole warp shares (row,quarter)
    }
}

// ---------------------------------------------------------------------------
// K2: finalize. 32K threads, one per (b,i) row:
//   dv = wh + sum(dvp[0..3]); v_new, new_h, new_trace_e.
// ---------------------------------------------------------------------------
__global__ __launch_bounds__(256) void k2_kernel(
    const float* __restrict__ v, const float* __restrict__ h,
    const float* __restrict__ trace_e, const float* __restrict__ tau_v,
    const float* __restrict__ tau_e, float* __restrict__ out) {
    const int r = blockIdx.x * 256 + threadIdx.x;  // b*512 + i
    const int i = r & 511;

    const float4 dp = *(const float4*)(g_dvp + (size_t)r * 4);
    const float dv  = g_wh[r] + ((dp.x + dp.y) + (dp.z + dp.w));

    const float sv  = sigmoidf_(tau_v[i]);
    const float se  = sigmoidf_(tau_e[i]);
    const float vb  = v[r];
    const float vn  = fmaf(sv, dv - vb, vb);
    const float te  = trace_e[r];
    const float nte = fmaf(se, h[r] - te, te);

    out[OFF_V   + r] = vn;
    out[OFF_NH  + r] = fmaxf(vn, 0.f);
    out[OFF_TEO + r] = nte;
}

// ---------------------------------------------------------------------------
// K3 (p2): pure streaming elementwise pass over the HxH matrices.
// 4 independent tasks per thread; trace_E via __ldcs; outputs via __stcs.
// dU is L2-warm from k1.
// ---------------------------------------------------------------------------
#define P2_BLOCKS 4096
#define P2_THREADS 256
#define P2_TOTAL  ((size_t)Bn * Hn * 128)
#define P2_QTR    (P2_TOTAL / 4)

__global__ __launch_bounds__(P2_THREADS) void p2_kernel(
    const float* __restrict__ dU, const float* __restrict__ trace_E,
    const float* __restrict__ h, const float* __restrict__ trace_e,
    float* __restrict__ out) {
    const size_t gid = (size_t)blockIdx.x * P2_THREADS + threadIdx.x;
    const float sE  = g_sE;
    const float omU = g_omU;

    const float4* dU4 = (const float4*)dU;
    const float4* tE4 = (const float4*)trace_E;
    const float4* h4p = (const float4*)h;
    const float4* te4p = (const float4*)trace_e;
    const float4* up4 = (const float4*)g_up;
    const float4* lo4 = (const float4*)g_lo;
    float4* outDU = (float4*)(out + OFF_DU);
    float4* outTE = (float4*)(out + OFF_TEE);

#pragma unroll
    for (int q = 0; q < 4; q++) {
        const size_t t = gid + (size_t)q * P2_QTR;
        const int j4  = (int)(t & 127);
        const size_t row = t >> 7;           // b*512 + i
        const int i = (int)(row & 511);
        const int b = (int)(row >> 9);

        const float4 du = dU4[t];
        const float4 tE = __ldcs(&tE4[t]);
        const float4 hh = h4p[((size_t)b << 7) + j4];
        const float4 te = te4p[((size_t)b << 7) + j4];
        const float4 up = up4[((size_t)i << 7) + j4];
        const float4 lo = lo4[((size_t)i << 7) + j4];
        const float nh  = __ldg(out + OFF_NH  + row);
        const float nte = __ldg(out + OFF_TEO + row);
        const float suMod = g_suMod[b];

        float4 tOut, dOut;
        {
            const float o = nh * te.x - nte * hh.x;
            tOut.x = fmaf(sE, o - tE.x, tE.x);
            dOut.x = fmaxf(fminf(fmaf(suMod, tOut.x, omU * du.x), up.x), lo.x);
        }
        {
            const float o = nh * te.y - nte * hh.y;
            tOut.y = fmaf(sE, o - tE.y, tE.y);
            dOut.y = fmaxf(fminf(fmaf(suMod, tOut.y, omU * du.y), up.y), lo.y);
        }
        {
            const float o = nh * te.z - nte * hh.z;
            tOut.z = fmaf(sE, o - tE.z, tE.z);
            dOut.z = fmaxf(fminf(fmaf(suMod, tOut.z, omU * du.z), up.z), lo.z);
        }
        {
            const float o = nh * te.w - nte * hh.w;
            tOut.w = fmaf(sE, o - tE.w, tE.w);
            dOut.w = fmaxf(fminf(fmaf(suMod, tOut.w, omU * du.w), up.w), lo.w);
        }
        __stcs(&outTE[t], tOut);
        __stcs(&outDU[t], dOut);
    }
}

extern "C" void kernel_launch(void* const* d_in, const int* in_sizes, int n_in,
                              void* d_out, int out_size) {
    const float* x       = (const float*)d_in[0];
    const float* h       = (const float*)d_in[1];
    const float* v       = (const float*)d_in[2];
    const float* dU      = (const float*)d_in[3];
    const float* trace_e = (const float*)d_in[4];
    const float* trace_E = (const float*)d_in[5];
    const float* x2h_w   = (const float*)d_in[6];
    const float* x2h_b   = (const float*)d_in[7];
    const float* h2h_w   = (const float*)d_in[8];
    const float* h2h_b   = (const float*)d_in[9];
    const float* alpha   = (const float*)d_in[10];
    const float* tau_v   = (const float*)d_in[11];
    const float* tau_e   = (const float*)d_in[12];
    const float* tau_U   = (const float*)d_in[13];
    const float* tau_E   = (const float*)d_in[14];
    float* out = (float*)d_out;

    k1_kernel<<<384 + PL_BLOCKS, 256>>>(x, h, dU, x2h_w, x2h_b, h2h_w, h2h_b,
                                        alpha, tau_U, tau_E);
    k2_kernel<<<(Bn * Hn) / 256, 256>>>(v, h, trace_e, tau_v, tau_e, out);
    p2_kernel<<<P2_BLOCKS, P2_THREADS>>>(dU, trace_E, h, trace_e, out);
}

// round 13
// speedup vs baseline: 1.2199x; 1.2199x over previous
#include <cuda_runtime.h>
#include <math.h>
#include <stdint.h>

#define Bn 64
#define Dn 256
#define Hn 512
#define Rn 32
#define CLIPV 50.0f

// Output layout (concatenation of the returned tuple, fp32):
//   v_new      [64,512]      @ 0
//   new_h      [64,512]      @ 32768
//   dU_new     [64,512,512]  @ 65536
//   new_trace_e[64,512]      @ 16842752
//   new_trace_E[64,512,512]  @ 16875520
#define OFF_V    ((size_t)0)
#define OFF_NH   ((size_t)32768)
#define OFF_DU   ((size_t)65536)
#define OFF_TEO  ((size_t)16842752)
#define OFF_TEE  ((size_t)16875520)

// Device-global scratch (allocation-free; fully rewritten every launch)
__device__ float g_up[Hn * Hn];
__device__ float g_lo[Hn * Hn];
__device__ float g_suMod[Bn];
__device__ float g_sE;
__device__ float g_omU;
__device__ float g_wh[Bn * Hn];        // bias + Wx + Wh per (b,i)
__device__ float g_dvp[Bn * Hn * 4];   // plastic partials, 4 quarters/row

__device__ __forceinline__ float sigmoidf_(float x) {
    return 1.0f / (1.0f + expf(-x));
}

// ---------------------------------------------------------------------------
// K1: one launch, 4928 blocks x 256 threads, reg-capped to keep the plastic
// stream at p2-like occupancy (R12's 78-reg/28%-occ failure mode removed).
//  [0,512)    Wh blocks: block bw owns i=bw; warp w covers batches w*8..w*8+7
//             (8 serial rows/warp, not 64 -> no long tail). W rows L1-hot.
//  [512,576)  mod blocks: g_suMod[b] (+ scalars at b==0).
//  [576,832)  uplo blocks: clip bounds, 2 i-rows per block.
//  [832,4928) plastic blocks: p2-shaped stream over dU. Warp covers a
//             quarter-row per q-step; one 5-shfl reduce; lane0 writes
//             g_dvp[row*4+quarter]. Deterministic, no atomics, no waits.
// ---------------------------------------------------------------------------
#define PL_BLOCKS 4096
#define PL_QTR    ((size_t)1048576)   // (64*512*128)/4 float4 tasks per q

__global__ __launch_bounds__(256, 6) void k1_kernel(
    const float* __restrict__ x, const float* __restrict__ h,
    const float* __restrict__ dU, const float* __restrict__ x2h_w,
    const float* __restrict__ x2h_b, const float* __restrict__ h2h_w,
    const float* __restrict__ h2h_b, const float* __restrict__ alpha,
    const float* __restrict__ tau_U, const float* __restrict__ tau_E) {
    const int bx   = blockIdx.x;
    const int tid  = threadIdx.x;
    const int warp = tid >> 5;
    const int lane = tid & 31;

    if (bx < 512) {
        // ---- Wh blocks: i = bx; warp w -> batches w*8 .. w*8+7 ----
        const int i  = bx;
        const float bias = x2h_b[i] + h2h_b[i];
        const float4* wrow4  = (const float4*)(h2h_w + (size_t)i * Hn);
        const float4* xwrow4 = (const float4*)(x2h_w + (size_t)i * Dn);

#pragma unroll
        for (int bb = 0; bb < 8; bb++) {
            const int b = warp * 8 + bb;
            const float4* hb4 = (const float4*)(h + (size_t)b * Hn);
            const float4* xb4 = (const float4*)(x + (size_t)b * Dn);
            float p0 = 0.f, p1 = 0.f, p2 = 0.f, p3 = 0.f;
#pragma unroll
            for (int c = 0; c < 4; c++) {
                const float4 W4 = __ldg(wrow4 + c * 32 + lane);
                const float4 H4 = __ldg(hb4 + c * 32 + lane);
                p0 = fmaf(W4.x, H4.x, p0);
                p1 = fmaf(W4.y, H4.y, p1);
                p2 = fmaf(W4.z, H4.z, p2);
                p3 = fmaf(W4.w, H4.w, p3);
            }
#pragma unroll
            for (int c = 0; c < 2; c++) {
                const float4 XW = __ldg(xwrow4 + c * 32 + lane);
                const float4 X4 = __ldg(xb4 + c * 32 + lane);
                p0 = fmaf(XW.x, X4.x, p0);
                p1 = fmaf(XW.y, X4.y, p1);
                p2 = fmaf(XW.z, X4.z, p2);
                p3 = fmaf(XW.w, X4.w, p3);
            }
            float p = (p0 + p1) + (p2 + p3);
#pragma unroll
            for (int off = 16; off; off >>= 1)
                p += __shfl_xor_sync(0xffffffffu, p, off);
            if (lane == 0) g_wh[(size_t)b * Hn + i] = p + bias;
        }
        return;
    }

    if (bx < 576) {
        // ---- mod blocks: b = bx - 512; 8 warps x 4 gate rows ----
        const int b = bx - 512;
        __shared__ float sm[8];
        const float4* xb = (const float4*)(x + (size_t)b * Dn);
        const float4* hb = (const float4*)(h + (size_t)b * Hn);

        float acc = 0.f;
#pragma unroll
        for (int t = 0; t < 4; t++) {
            const int r = warp + 8 * t;          // 8 warps x 4 rows = 32
            const int o = Hn + r;
            const float4* xw = (const float4*)(x2h_w + (size_t)o * Dn);
            const float4* hw = (const float4*)(h2h_w + (size_t)o * Hn);
            float s = 0.f;
#pragma unroll
            for (int c = 0; c < 2; c++) {
                const float4 W4 = xw[c * 32 + lane];
                const float4 V4 = xb[c * 32 + lane];
                s = fmaf(W4.x, V4.x, s); s = fmaf(W4.y, V4.y, s);
                s = fmaf(W4.z, V4.z, s); s = fmaf(W4.w, V4.w, s);
            }
#pragma unroll
            for (int c = 0; c < 4; c++) {
                const float4 W4 = hw[c * 32 + lane];
                const float4 V4 = hb[c * 32 + lane];
                s = fmaf(W4.x, V4.x, s); s = fmaf(W4.y, V4.y, s);
                s = fmaf(W4.z, V4.z, s); s = fmaf(W4.w, V4.w, s);
            }
#pragma unroll
            for (int off = 16; off; off >>= 1)
                s += __shfl_xor_sync(0xffffffffu, s, off);
            if (lane == 0) acc += fmaxf(s + x2h_b[o] + h2h_b[o], 0.f);
        }
        if (lane == 0) sm[warp] = acc;
        __syncthreads();
        if (tid == 0) {
            float m = 0.f;
#pragma unroll
            for (int w = 0; w < 8; w++) m += sm[w];
            const float sU = sigmoidf_(tau_U[0]);
            g_suMod[b] = sU * m;
            if (b == 0) {
                g_sE  = sigmoidf_(tau_E[0]);
                g_omU = 1.0f - sU;
            }
        }
        return;
    }

    if (bx < 832) {
        // ---- uplo blocks: 2 i-rows per block ----
        const int i  = (bx - 576) * 2 + (tid >> 7);
        const int j0 = (tid & 127) * 4;
        const float4 W = __ldg((const float4*)(h2h_w + (size_t)i * Hn + j0));
        const float4 A = __ldg((const float4*)(alpha + (size_t)i * Hn + j0));
        float4 up, lo;
        {
            const float d = fmaxf(A.x, 0.f) + 1e-8f;
            up.x = fmaxf(CLIPV - W.x, 0.f) / d;
            lo.x = -fmaxf(CLIPV + W.x, 0.f) / d;
        }
        {
            const float d = fmaxf(A.y, 0.f) + 1e-8f;
            up.y = fmaxf(CLIPV - W.y, 0.f) / d;
            lo.y = -fmaxf(CLIPV + W.y, 0.f) / d;
        }
        {
            const float d = fmaxf(A.z, 0.f) + 1e-8f;
            up.z = fmaxf(CLIPV - W.z, 0.f) / d;
            lo.z = -fmaxf(CLIPV + W.z, 0.f) / d;
        }
        {
            const float d = fmaxf(A.w, 0.f) + 1e-8f;
            up.w = fmaxf(CLIPV - W.w, 0.f) / d;
            lo.w = -fmaxf(CLIPV + W.w, 0.f) / d;
        }
        *(float4*)(g_up + (size_t)i * Hn + j0) = up;
        *(float4*)(g_lo + (size_t)i * Hn + j0) = lo;
        return;
    }

    // ---- plastic blocks: p2-shaped stream over dU ----
    const size_t gid = (size_t)(bx - 832) * 256 + tid;
    const float4* dU4 = (const float4*)dU;
    const float4* a4p = (const float4*)alpha;
    const float4* h4p = (const float4*)h;

#pragma unroll
    for (int q = 0; q < 4; q++) {
        const size_t t = gid + (size_t)q * PL_QTR;
        const int j4  = (int)(t & 127);
        const size_t row = t >> 7;           // b*512 + i
        const int quarter = (int)((t >> 5) & 3);
        const int i = (int)(row & 511);
        const int b = (int)(row >> 9);

        const float4 du = dU4[t];            // default cache: L2-warm for p2
        const float4 a4 = __ldg(&a4p[((size_t)i << 7) + j4]);
        const float4 h4 = __ldg(&h4p[((size_t)b << 7) + j4]);

        float s;
        s = fmaxf(a4.x, 0.f) * du.x * h4.x;
        s = fmaf(fmaxf(a4.y, 0.f) * du.y, h4.y, s);
        s = fmaf(fmaxf(a4.z, 0.f) * du.z, h4.z, s);
        s = fmaf(fmaxf(a4.w, 0.f) * du.w, h4.w, s);
#pragma unroll
        for (int off = 16; off; off >>= 1)
            s += __shfl_xor_sync(0xffffffffu, s, off);
        if (lane == 0) g_dvp[row * 4 + quarter] = s;
    }
}

// ---------------------------------------------------------------------------
// K2: finalize. One thread per (b,i) row:
//   dv = wh + sum(dvp[0..3]); v_new, new_h, new_trace_e.
// ---------------------------------------------------------------------------
__global__ __launch_bounds__(256) void k2_kernel(
    const float* __restrict__ v, const float* __restrict__ h,
    const float* __restrict__ trace_e, const float* __restrict__ tau_v,
    const float* __restrict__ tau_e, float* __restrict__ out) {
    const int r = blockIdx.x * 256 + threadIdx.x;  // b*512 + i
    const int i = r & 511;

    const float4 dp = *(const float4*)(g_dvp + (size_t)r * 4);
    const float dv  = g_wh[r] + ((dp.x + dp.y) + (dp.z + dp.w));

    const float sv  = sigmoidf_(tau_v[i]);
    const float se  = sigmoidf_(tau_e[i]);
    const float vb  = v[r];
    const float vn  = fmaf(sv, dv - vb, vb);
    const float te  = trace_e[r];
    const float nte = fmaf(se, h[r] - te, te);

    out[OFF_V   + r] = vn;
    out[OFF_NH  + r] = fmaxf(vn, 0.f);
    out[OFF_TEO + r] = nte;
}

// ---------------------------------------------------------------------------
// K3 (p2): pure streaming elementwise pass over the HxH matrices.
// 4 independent tasks per thread; trace_E via __ldcs; outputs via __stcs.
// dU is L2-warm from k1.
// ---------------------------------------------------------------------------
#define P2_BLOCKS 4096
#define P2_THREADS 256
#define P2_TOTAL  ((size_t)Bn * Hn * 128)
#define P2_QTR2   (P2_TOTAL / 4)

__global__ __launch_bounds__(P2_THREADS) void p2_kernel(
    const float* __restrict__ dU, const float* __restrict__ trace_E,
    const float* __restrict__ h, const float* __restrict__ trace_e,
    float* __restrict__ out) {
    const size_t gid = (size_t)blockIdx.x * P2_THREADS + threadIdx.x;
    const float sE  = g_sE;
    const float omU = g_omU;

    const float4* dU4 = (const float4*)dU;
    const float4* tE4 = (const float4*)trace_E;
    const float4* h4p = (const float4*)h;
    const float4* te4p = (const float4*)trace_e;
    const float4* up4 = (const float4*)g_up;
    const float4* lo4 = (const float4*)g_lo;
    float4* outDU = (float4*)(out + OFF_DU);
    float4* outTE = (float4*)(out + OFF_TEE);

#pragma unroll
    for (int q = 0; q < 4; q++) {
        const size_t t = gid + (size_t)q * P2_QTR2;
        const int j4  = (int)(t & 127);
        const size_t row = t >> 7;           // b*512 + i
        const int i = (int)(row & 511);
        const int b = (int)(row >> 9);

        const float4 du = dU4[t];
        const float4 tE = __ldcs(&tE4[t]);
        const float4 hh = h4p[((size_t)b << 7) + j4];
        const float4 te = te4p[((size_t)b << 7) + j4];
        const float4 up = up4[((size_t)i << 7) + j4];
        const float4 lo = lo4[((size_t)i << 7) + j4];
        const float nh  = __ldg(out + OFF_NH  + row);
        const float nte = __ldg(out + OFF_TEO + row);
        const float suMod = g_suMod[b];

        float4 tOut, dOut;
        {
            const float o = nh * te.x - nte * hh.x;
            tOut.x = fmaf(sE, o - tE.x, tE.x);
            dOut.x = fmaxf(fminf(fmaf(suMod, tOut.x, omU * du.x), up.x), lo.x);
        }
        {
            const float o = nh * te.y - nte * hh.y;
            tOut.y = fmaf(sE, o - tE.y, tE.y);
            dOut.y = fmaxf(fminf(fmaf(suMod, tOut.y, omU * du.y), up.y), lo.y);
        }
        {
            const float o = nh * te.z - nte * hh.z;
            tOut.z = fmaf(sE, o - tE.z, tE.z);
            dOut.z = fmaxf(fminf(fmaf(suMod, tOut.z, omU * du.z), up.z), lo.z);
        }
        {
            const float o = nh * te.w - nte * hh.w;
            tOut.w = fmaf(sE, o - tE.w, tE.w);
            dOut.w = fmaxf(fminf(fmaf(suMod, tOut.w, omU * du.w), up.w), lo.w);
        }
        __stcs(&outTE[t], tOut);
        __stcs(&outDU[t], dOut);
    }
}

extern "C" void kernel_launch(void* const* d_in, const int* in_sizes, int n_in,
                              void* d_out, int out_size) {
    const float* x       = (const float*)d_in[0];
    const float* h       = (const float*)d_in[1];
    const float* v       = (const float*)d_in[2];
    const float* dU      = (const float*)d_in[3];
    const float* trace_e = (const float*)d_in[4];
    const float* trace_E = (const float*)d_in[5];
    const float* x2h_w   = (const float*)d_in[6];
    const float* x2h_b   = (const float*)d_in[7];
    const float* h2h_w   = (const float*)d_in[8];
    const float* h2h_b   = (const float*)d_in[9];
    const float* alpha   = (const float*)d_in[10];
    const float* tau_v   = (const float*)d_in[11];
    const float* tau_e   = (const float*)d_in[12];
    const float* tau_U   = (const float*)d_in[13];
    const float* tau_E   = (const float*)d_in[14];
    float* out = (float*)d_out;

    k1_kernel<<<832 + PL_BLOCKS, 256>>>(x, h, dU, x2h_w, x2h_b, h2h_w, h2h_b,
                                        alpha, tau_U, tau_E);
    k2_kernel<<<(Bn * Hn) / 256, 256>>>(v, h, trace_e, tau_v, tau_e, out);
    p2_kernel<<<P2_BLOCKS, P2_THREADS>>>(dU, trace_E, h, trace_e, out);
}